// round 15
// baseline (speedup 1.0000x reference)
#include <cuda_runtime.h>
#include <cuda_fp16.h>
#include <cstdint>

#define BD 8
#define SD 2048
#define DD 1024
#define HD 1024
#define ED 2048
#define MD (BD * SD)
#define LAYERS 4

#define M_TILE 128
#define N_TILE 256
#define K_CHUNK 64
#define NCHUNK (DD / K_CHUNK)     // 16

#define ROW_B 144                 // 128B data + 16B pad
#define A_TILE_B (128 * ROW_B)    // 18432
#define W_TILE_B (256 * ROW_B)    // 36864
#define A_OFF 0
#define W_OFF A_TILE_B
#define STAGE_B (A_TILE_B + W_TILE_B)   // 55296
#define NSTAGE 2
#define SMEM_TOTAL (NSTAGE * STAGE_B)   // 110592 -> 2 CTAs/SM

__device__ __half g_gh[(size_t)MD * ED];
__device__ __half g_s0[(size_t)MD * HD];
__device__ __half g_s1[(size_t)MD * HD];
__device__ __half g_wh[(size_t)LAYERS * ED * DD];

__device__ __forceinline__ uint32_t smem_u32(const void* p) {
    uint32_t a;
    asm("{ .reg .u64 t; cvta.to.shared.u64 t, %1; cvt.u32.u64 %0, t; }"
        : "=r"(a) : "l"(p));
    return a;
}
__device__ __forceinline__ void cp16(uint32_t dst, const void* src) {
    asm volatile("cp.async.cg.shared.global [%0], [%1], 16;" :: "r"(dst), "l"(src));
}
__device__ __forceinline__ void ldsm4(uint32_t* r, uint32_t addr) {
    asm volatile("ldmatrix.sync.aligned.m8n8.x4.shared.b16 {%0,%1,%2,%3}, [%4];"
                 : "=r"(r[0]), "=r"(r[1]), "=r"(r[2]), "=r"(r[3]) : "r"(addr));
}
__device__ __forceinline__ void mma16816(float* c, const uint32_t* a,
                                         uint32_t b0, uint32_t b1) {
    asm volatile(
        "mma.sync.aligned.m16n8k16.row.col.f32.f16.f16.f32 "
        "{%0,%1,%2,%3}, {%4,%5,%6,%7}, {%8,%9}, {%0,%1,%2,%3};"
        : "+f"(c[0]), "+f"(c[1]), "+f"(c[2]), "+f"(c[3])
        : "r"(a[0]), "r"(a[1]), "r"(a[2]), "r"(a[3]), "r"(b0), "r"(b1));
}

// ---------------------------------------------------------------------------
// GEMM: CTA 128x256, 8 warps (2 wm x 4 wn), warp 64x64, K_CHUNK=64,
// 2-stage cp.async ring, 2 CTAs/SM (16 warps/SM).
// ---------------------------------------------------------------------------
__global__ __launch_bounds__(256, 2) void gemm_mma(
    const __half* __restrict__ A, const __half* __restrict__ W,
    const float* __restrict__ bias, __half* __restrict__ C)
{
    extern __shared__ char smem[];
    const uint32_t sbase = smem_u32(smem);
    const int tid  = threadIdx.x;
    const int wid  = tid >> 5;
    const int lane = tid & 31;
    const int g    = lane >> 2;
    const int t4   = lane & 3;
    const int wm   = wid >> 2;        // 0..1 : 64 m-rows
    const int wn   = wid & 3;         // 0..3 : 64 n-cols
    const int bm   = blockIdx.y * M_TILE;
    const int bn   = blockIdx.x * N_TILE;

    float acc[4][8][4];
#pragma unroll
    for (int i = 0; i < 4; i++)
#pragma unroll
        for (int j = 0; j < 8; j++)
#pragma unroll
            for (int q = 0; q < 4; q++) acc[i][j][q] = 0.f;

    auto fill = [&](int s, int c) {
        const uint32_t st = sbase + s * STAGE_B;
        const int k0 = c * K_CHUNK;
#pragma unroll
        for (int rep = 0; rep < 4; rep++) {           // A: 128 rows x 8 chunks
            const int v  = tid + rep * 256;
            const int r  = v >> 3, c8 = v & 7;
            cp16(st + A_OFF + r * ROW_B + c8 * 16,
                 A + (size_t)(bm + r) * DD + k0 + c8 * 8);
        }
#pragma unroll
        for (int rep = 0; rep < 8; rep++) {           // W: 256 rows x 8 chunks
            const int v  = tid + rep * 256;
            const int r  = v >> 3, c8 = v & 7;
            cp16(st + W_OFF + r * ROW_B + c8 * 16,
                 W + (size_t)(bn + r) * DD + k0 + c8 * 8);
        }
        asm volatile("cp.async.commit_group;" ::: "memory");
    };

    const uint32_t a_off = (uint32_t)(wm * 64 + (lane & 15)) * ROW_B
                         + ((lane >> 4) & 1) * 16;
    const uint32_t w_mi  = (uint32_t)(lane >> 3);
    const uint32_t w_off = (uint32_t)(wn * 64 + (w_mi >> 1) * 8 + (lane & 7)) * ROW_B
                         + (w_mi & 1) * 16;

    fill(0, 0);

#pragma unroll 1
    for (int c = 0; c < NCHUNK; c++) {
        if (c + 1 < NCHUNK) {
            fill((c + 1) & 1, c + 1);
            asm volatile("cp.async.wait_group 1;" ::: "memory");
        } else {
            asm volatile("cp.async.wait_group 0;" ::: "memory");
        }
        __syncthreads();

        const uint32_t st = sbase + (c & 1) * STAGE_B;
#pragma unroll
        for (int k16 = 0; k16 < 4; k16++) {
            const uint32_t kb = (uint32_t)k16 * 32;
            uint32_t wf[4][4];
#pragma unroll
            for (int jp = 0; jp < 4; jp++)
                ldsm4(wf[jp], st + W_OFF + w_off + jp * (16 * ROW_B) + kb);
#pragma unroll
            for (int mi = 0; mi < 4; mi++) {
                uint32_t af[4];
                ldsm4(af, st + A_OFF + a_off + mi * (16 * ROW_B) + kb);
#pragma unroll
                for (int jp = 0; jp < 4; jp++) {
                    mma16816(acc[mi][jp * 2],     af, wf[jp][0], wf[jp][1]);
                    mma16816(acc[mi][jp * 2 + 1], af, wf[jp][2], wf[jp][3]);
                }
            }
        }
        __syncthreads();
    }

    float bj[8][2];
#pragma unroll
    for (int j = 0; j < 8; j++) {
        const int col = bn + wn * 64 + j * 8 + 2 * t4;
        bj[j][0] = bias[col]; bj[j][1] = bias[col + 1];
    }
#pragma unroll
    for (int mi = 0; mi < 4; mi++) {
        const int r0 = bm + wm * 64 + mi * 16 + g;
#pragma unroll
        for (int j = 0; j < 8; j++) {
            const int col = bn + wn * 64 + j * 8 + 2 * t4;
            __half2 v0 = __floats2half2_rn(acc[mi][j][0] + bj[j][0],
                                           acc[mi][j][1] + bj[j][1]);
            __half2 v1 = __floats2half2_rn(acc[mi][j][2] + bj[j][0],
                                           acc[mi][j][3] + bj[j][1]);
            *(__half2*)(C + (size_t)r0 * ED + col)       = v0;
            *(__half2*)(C + (size_t)(r0 + 8) * ED + col) = v1;
        }
    }
}

// ---------------------------------------------------------------------------
__global__ __launch_bounds__(256) void conv_x(
    const float* __restrict__ src, __half* __restrict__ dst, size_t n)
{
    for (size_t i = (size_t)blockIdx.x * blockDim.x + threadIdx.x; i < n;
         i += (size_t)gridDim.x * blockDim.x)
        dst[i] = __float2half_rn(src[i]);
}

__global__ __launch_bounds__(256) void conv_w(
    const float* __restrict__ W0, const float* __restrict__ Wl,
    __half* __restrict__ dst)
{
    const size_t per = (size_t)ED * DD;
    const size_t n = (size_t)LAYERS * per;
    for (size_t i = (size_t)blockIdx.x * blockDim.x + threadIdx.x; i < n;
         i += (size_t)gridDim.x * blockDim.x)
        dst[i] = __float2half_rn((i < per) ? W0[i] : Wl[i - per]);
}

// ---------------------------------------------------------------------------
// Scan half2 with MUFU.TANH sigmoid (unchanged).
// ---------------------------------------------------------------------------
__device__ __forceinline__ float sigf(float x) {
    float t;
    asm("tanh.approx.f32 %0, %1;" : "=f"(t) : "f"(0.5f * x));
    return fmaf(0.5f, t, 0.5f);
}
__device__ __forceinline__ float gact(float x) { return (x >= 0.f) ? (x + 0.5f) : sigf(x); }

#define SC_LANES 16
#define SC_NC    64
#define SC_CH    (SD / SC_NC)   // 32

__global__ __launch_bounds__(1024) void scan_h2(
    const __half2* __restrict__ gh,
    const void* __restrict__ inp,
    const float* __restrict__ h0,
    void* __restrict__ outp,
    float* __restrict__ finals, int ip_f32, int out_f32)
{
    const int b  = blockIdx.y;
    const int hx = threadIdx.x & (SC_LANES - 1);
    const int tc = threadIdx.x / SC_LANES;
    const int p  = blockIdx.x * SC_LANES + hx;
    const int t0 = tc * SC_CH;

    const size_t rowbase = (size_t)b * SD;
    const __half2* gp = gh + (rowbase + t0) * (ED / 2) + p;
    const __half2* hp = gp + HD / 2;

    float2 Ac = {1.f, 1.f}, Cc = {0.f, 0.f};
#pragma unroll 8
    for (int j = 0; j < SC_CH; j++) {
        const size_t off = (size_t)j * (ED / 2);
        const float2 zg  = __half22float2(gp[off]);
        const float2 hid = __half22float2(hp[off]);
        const float zx = sigf(zg.x), zy = sigf(zg.y);
        const float ax = 1.f - zx, ay = 1.f - zy;
        Cc.x = fmaf(ax, Cc.x, zx * gact(hid.x));
        Cc.y = fmaf(ay, Cc.y, zy * gact(hid.y));
        Ac.x *= ax; Ac.y *= ay;
    }

    __shared__ float2 sA[SC_NC][SC_LANES + 1], sC[SC_NC][SC_LANES + 1];
    sA[tc][hx] = Ac; sC[tc][hx] = Cc;
    __syncthreads();

    const float2 hprev = *(const float2*)(h0 + b * HD + 2 * p);
    float2 hcur = { gact(hprev.x), gact(hprev.y) };
    for (int c = 0; c < tc; c++) {
        const float2 a = sA[c][hx], cc = sC[c][hx];
        hcur.x = fmaf(a.x, hcur.x, cc.x);
        hcur.y = fmaf(a.y, hcur.y, cc.y);
    }

    const size_t obase = (rowbase + t0) * (HD / 2) + p;
#pragma unroll 8
    for (int j = 0; j < SC_CH; j++) {
        const size_t off = (size_t)j * (ED / 2);
        const float2 zg  = __half22float2(gp[off]);
        const float2 hid = __half22float2(hp[off]);
        const float zx = sigf(zg.x), zy = sigf(zg.y);
        hcur.x = fmaf(1.f - zx, hcur.x, zx * gact(hid.x));
        hcur.y = fmaf(1.f - zy, hcur.y, zy * gact(hid.y));

        const size_t idx = obase + (size_t)j * (HD / 2);
        float2 ipv;
        if (ip_f32) ipv = ((const float2*)inp)[idx];
        else        ipv = __half22float2(((const __half2*)inp)[idx]);
        const float2 o = { hcur.x + ipv.x, hcur.y + ipv.y };
        if (out_f32) ((float2*)outp)[idx] = o;
        else         ((__half2*)outp)[idx] = __floats2half2_rn(o.x, o.y);
    }
    if (tc == SC_NC - 1) *(float2*)(finals + b * HD + 2 * p) = hcur;
}

// ---------------------------------------------------------------------------
extern "C" void kernel_launch(void* const* d_in, const int* in_sizes, int n_in,
                              void* d_out, int out_size)
{
    const float* x  = (const float*)d_in[0];
    const float* h  = (const float*)d_in[1];
    const float* W0 = (const float*)d_in[2];
    const float* b0 = (const float*)d_in[3];
    const float* Wl = (const float*)d_in[4];
    const float* bl = (const float*)d_in[5];

    float* out    = (float*)d_out;
    float* finals = out + (size_t)MD * HD;

    __half *gh, *s0, *s1, *wh;
    cudaGetSymbolAddress((void**)&gh, g_gh);
    cudaGetSymbolAddress((void**)&s0, g_s0);
    cudaGetSymbolAddress((void**)&s1, g_s1);
    cudaGetSymbolAddress((void**)&wh, g_wh);

    cudaFuncSetAttribute(gemm_mma, cudaFuncAttributeMaxDynamicSharedMemorySize,
                         SMEM_TOTAL);

    conv_w<<<512, 256>>>(W0, Wl, wh);
    conv_x<<<512, 256>>>(x, s0, (size_t)MD * DD);

    const dim3 ggrid(ED / N_TILE, MD / M_TILE);         // (8, 128)
    const dim3 sgrid(HD / 2 / SC_LANES, BD);            // (32, 8)

    __half* Astream[LAYERS + 1] = { s0, s1, s0, s1, s0 };
    for (int l = 0; l < LAYERS; l++) {
        const size_t woff = (size_t)l * ED * DD;
        const float* bb = (l == 0) ? b0 : bl + (size_t)(l - 1) * ED;
        const int last = (l == LAYERS - 1);

        gemm_mma<<<ggrid, 256, SMEM_TOTAL>>>(Astream[l], wh + woff, bb, gh);
        scan_h2<<<sgrid, 1024>>>(
            (const __half2*)gh,
            (l == 0) ? (const void*)x : (const void*)Astream[l],
            h + (size_t)l * BD * HD,
            last ? (void*)out : (void*)Astream[l + 1],
            finals + (size_t)l * BD * HD,
            (l == 0) ? 1 : 0, last ? 1 : 0);
    }
}

// round 16
// speedup vs baseline: 2.5878x; 2.5878x over previous
#include <cuda_runtime.h>
#include <cuda_fp16.h>
#include <cstdint>

#define BD 8
#define SD 2048
#define DD 1024
#define HD 1024
#define ED 2048
#define MD (BD * SD)
#define LAYERS 4

#define M_TILE 128
#define N_TILE 128
#define K_CHUNK 64
#define NCHUNK (DD / K_CHUNK)     // 16

#define ROW_B 144
#define A_TILE_B (128 * ROW_B)
#define W_TILE_B (128 * ROW_B)
#define A_OFF 0
#define W_OFF A_TILE_B
#define STAGE_B (A_TILE_B + W_TILE_B)   // 36864
#define NSTAGE 3
#define SMEM_TOTAL (NSTAGE * STAGE_B)   // 110592 -> 2 CTAs/SM

__device__ __half g_gh[(size_t)MD * ED];
__device__ __half g_s0[(size_t)MD * HD];
__device__ __half g_s1[(size_t)MD * HD];
__device__ __half g_wh[(size_t)LAYERS * ED * DD];

__device__ __forceinline__ uint32_t smem_u32(const void* p) {
    uint32_t a;
    asm("{ .reg .u64 t; cvta.to.shared.u64 t, %1; cvt.u32.u64 %0, t; }"
        : "=r"(a) : "l"(p));
    return a;
}
__device__ __forceinline__ void cp16(uint32_t dst, const void* src) {
    asm volatile("cp.async.cg.shared.global [%0], [%1], 16;" :: "r"(dst), "l"(src));
}
__device__ __forceinline__ void ldsm4(uint32_t* r, uint32_t addr) {
    asm volatile("ldmatrix.sync.aligned.m8n8.x4.shared.b16 {%0,%1,%2,%3}, [%4];"
                 : "=r"(r[0]), "=r"(r[1]), "=r"(r[2]), "=r"(r[3]) : "r"(addr));
}
__device__ __forceinline__ void mma16816(float* c, const uint32_t* a,
                                         uint32_t b0, uint32_t b1) {
    asm volatile(
        "mma.sync.aligned.m16n8k16.row.col.f32.f16.f16.f32 "
        "{%0,%1,%2,%3}, {%4,%5,%6,%7}, {%8,%9}, {%0,%1,%2,%3};"
        : "+f"(c[0]), "+f"(c[1]), "+f"(c[2]), "+f"(c[3])
        : "r"(a[0]), "r"(a[1]), "r"(a[2]), "r"(a[3]), "r"(b0), "r"(b1));
}

// ---------------------------------------------------------------------------
// GEMM (R12 champion, byte-identical): CTA 128x128, 8 warps (2x4),
// warp 64x32, K_CHUNK=64, 3-stage ring, 2 CTAs/SM.
// ---------------------------------------------------------------------------
__global__ __launch_bounds__(256, 2) void gemm_mma(
    const __half* __restrict__ A, const __half* __restrict__ W,
    const float* __restrict__ bias, __half* __restrict__ C)
{
    extern __shared__ char smem[];
    const uint32_t sbase = smem_u32(smem);
    const int tid  = threadIdx.x;
    const int wid  = tid >> 5;
    const int lane = tid & 31;
    const int g    = lane >> 2;
    const int t4   = lane & 3;
    const int wm   = wid >> 2;
    const int wn   = wid & 3;
    const int bm   = blockIdx.y * M_TILE;
    const int bn   = blockIdx.x * N_TILE;

    float acc[4][4][4];
#pragma unroll
    for (int i = 0; i < 4; i++)
#pragma unroll
        for (int j = 0; j < 4; j++)
#pragma unroll
            for (int q = 0; q < 4; q++) acc[i][j][q] = 0.f;

    auto fill = [&](int s, int c) {
        const uint32_t st = sbase + s * STAGE_B;
        const int k0 = c * K_CHUNK;
#pragma unroll
        for (int rep = 0; rep < 4; rep++) {
            const int v  = tid + rep * 256;
            const int r  = v >> 3, c8 = v & 7;
            cp16(st + A_OFF + r * ROW_B + c8 * 16,
                 A + (size_t)(bm + r) * DD + k0 + c8 * 8);
        }
#pragma unroll
        for (int rep = 0; rep < 4; rep++) {
            const int v  = tid + rep * 256;
            const int r  = v >> 3, c8 = v & 7;
            cp16(st + W_OFF + r * ROW_B + c8 * 16,
                 W + (size_t)(bn + r) * DD + k0 + c8 * 8);
        }
        asm volatile("cp.async.commit_group;" ::: "memory");
    };

    const uint32_t a_off = (uint32_t)(wm * 64 + (lane & 15)) * ROW_B
                         + ((lane >> 4) & 1) * 16;
    const uint32_t w_mi  = (uint32_t)(lane >> 3);
    const uint32_t w_off = (uint32_t)(wn * 32 + (w_mi >> 1) * 8 + (lane & 7)) * ROW_B
                         + (w_mi & 1) * 16;

    fill(0, 0);
    fill(1, 1);

#pragma unroll 1
    for (int c = 0; c < NCHUNK; c++) {
        if (c + 1 < NCHUNK)
            asm volatile("cp.async.wait_group 1;" ::: "memory");
        else
            asm volatile("cp.async.wait_group 0;" ::: "memory");
        __syncthreads();

        if (c + 2 < NCHUNK) fill((c + 2) % NSTAGE, c + 2);

        const uint32_t st = sbase + (c % NSTAGE) * STAGE_B;
#pragma unroll
        for (int k16 = 0; k16 < 4; k16++) {
            const uint32_t kb = (uint32_t)k16 * 32;
            uint32_t wf[2][4];
#pragma unroll
            for (int jp = 0; jp < 2; jp++)
                ldsm4(wf[jp], st + W_OFF + w_off + jp * (16 * ROW_B) + kb);
#pragma unroll
            for (int mi = 0; mi < 4; mi++) {
                uint32_t af[4];
                ldsm4(af, st + A_OFF + a_off + mi * (16 * ROW_B) + kb);
#pragma unroll
                for (int jp = 0; jp < 2; jp++) {
                    mma16816(acc[mi][jp * 2],     af, wf[jp][0], wf[jp][1]);
                    mma16816(acc[mi][jp * 2 + 1], af, wf[jp][2], wf[jp][3]);
                }
            }
        }
    }

    float bj[4][2];
#pragma unroll
    for (int j = 0; j < 4; j++) {
        const int col = bn + wn * 32 + j * 8 + 2 * t4;
        bj[j][0] = bias[col]; bj[j][1] = bias[col + 1];
    }
#pragma unroll
    for (int mi = 0; mi < 4; mi++) {
        const int r0 = bm + wm * 64 + mi * 16 + g;
#pragma unroll
        for (int j = 0; j < 4; j++) {
            const int col = bn + wn * 32 + j * 8 + 2 * t4;
            __half2 v0 = __floats2half2_rn(acc[mi][j][0] + bj[j][0],
                                           acc[mi][j][1] + bj[j][1]);
            __half2 v1 = __floats2half2_rn(acc[mi][j][2] + bj[j][0],
                                           acc[mi][j][3] + bj[j][1]);
            *(__half2*)(C + (size_t)r0 * ED + col)       = v0;
            *(__half2*)(C + (size_t)(r0 + 8) * ED + col) = v1;
        }
    }
}

// ---------------------------------------------------------------------------
__global__ __launch_bounds__(256) void conv_x(
    const float4* __restrict__ src, __half2* __restrict__ dst, size_t n4)
{
    for (size_t i = (size_t)blockIdx.x * blockDim.x + threadIdx.x; i < n4;
         i += (size_t)gridDim.x * blockDim.x) {
        const float4 v = src[i];
        dst[2 * i]     = __floats2half2_rn(v.x, v.y);
        dst[2 * i + 1] = __floats2half2_rn(v.z, v.w);
    }
}

__global__ __launch_bounds__(256) void conv_w(
    const float* __restrict__ W0, const float* __restrict__ Wl,
    __half* __restrict__ dst)
{
    const size_t per = (size_t)ED * DD;
    const size_t n = (size_t)LAYERS * per;
    for (size_t i = (size_t)blockIdx.x * blockDim.x + threadIdx.x; i < n;
         i += (size_t)gridDim.x * blockDim.x)
        dst[i] = __float2half_rn((i < per) ? W0[i] : Wl[i - per]);
}

// ---------------------------------------------------------------------------
// Scan float4 (4 h-values per lane): 8 f4-lanes x 128 chunks (1024 thr),
// CH=16. grid (32, 8). MUFU.TANH sigmoid.
// ---------------------------------------------------------------------------
__device__ __forceinline__ float sigf(float x) {
    float t;
    asm("tanh.approx.f32 %0, %1;" : "=f"(t) : "f"(0.5f * x));
    return fmaf(0.5f, t, 0.5f);
}
__device__ __forceinline__ float gact(float x) { return (x >= 0.f) ? (x + 0.5f) : sigf(x); }

#define SC_LANES 8
#define SC_NC    128
#define SC_CH    (SD / SC_NC)   // 16

struct h4 { __half2 a, b; };          // 4 halfs = 8 bytes

__device__ __forceinline__ float4 h4_to_f4(h4 v) {
    const float2 lo = __half22float2(v.a), hi = __half22float2(v.b);
    return make_float4(lo.x, lo.y, hi.x, hi.y);
}

__global__ __launch_bounds__(1024) void scan_f4(
    const h4* __restrict__ gh,        // rows of ED/4 h4
    const void* __restrict__ inp,     // fp32 or half stream
    const float* __restrict__ h0,
    void* __restrict__ outp,
    float* __restrict__ finals, int ip_f32, int out_f32)
{
    const int b  = blockIdx.y;
    const int hx = threadIdx.x & (SC_LANES - 1);
    const int tc = threadIdx.x / SC_LANES;        // 0..127
    const int p  = blockIdx.x * SC_LANES + hx;    // h4 column (0..HD/4-1)
    const int t0 = tc * SC_CH;

    const size_t rowbase = (size_t)b * SD;
    const h4* gp = gh + (rowbase + t0) * (ED / 4) + p;
    const h4* hp = gp + HD / 4;

    float4 Ac = {1.f, 1.f, 1.f, 1.f}, Cc = {0.f, 0.f, 0.f, 0.f};
#pragma unroll 8
    for (int j = 0; j < SC_CH; j++) {
        const size_t off = (size_t)j * (ED / 4);
        const float4 zg  = h4_to_f4(gp[off]);
        const float4 hid = h4_to_f4(hp[off]);
        const float z0 = sigf(zg.x), z1 = sigf(zg.y), z2 = sigf(zg.z), z3 = sigf(zg.w);
        const float a0 = 1.f - z0, a1 = 1.f - z1, a2 = 1.f - z2, a3 = 1.f - z3;
        Cc.x = fmaf(a0, Cc.x, z0 * gact(hid.x));
        Cc.y = fmaf(a1, Cc.y, z1 * gact(hid.y));
        Cc.z = fmaf(a2, Cc.z, z2 * gact(hid.z));
        Cc.w = fmaf(a3, Cc.w, z3 * gact(hid.w));
        Ac.x *= a0; Ac.y *= a1; Ac.z *= a2; Ac.w *= a3;
    }

    __shared__ float4 sA[SC_NC][SC_LANES + 1], sC[SC_NC][SC_LANES + 1];
    sA[tc][hx] = Ac; sC[tc][hx] = Cc;
    __syncthreads();

    const float4 hprev = *(const float4*)(h0 + b * HD + 4 * p);
    float4 hcur = { gact(hprev.x), gact(hprev.y), gact(hprev.z), gact(hprev.w) };
    for (int c = 0; c < tc; c++) {
        const float4 a = sA[c][hx], cc = sC[c][hx];
        hcur.x = fmaf(a.x, hcur.x, cc.x);
        hcur.y = fmaf(a.y, hcur.y, cc.y);
        hcur.z = fmaf(a.z, hcur.z, cc.z);
        hcur.w = fmaf(a.w, hcur.w, cc.w);
    }

    const size_t obase = (rowbase + t0) * (HD / 4) + p;
#pragma unroll 8
    for (int j = 0; j < SC_CH; j++) {
        const size_t off = (size_t)j * (ED / 4);
        const float4 zg  = h4_to_f4(gp[off]);
        const float4 hid = h4_to_f4(hp[off]);
        const float z0 = sigf(zg.x), z1 = sigf(zg.y), z2 = sigf(zg.z), z3 = sigf(zg.w);
        hcur.x = fmaf(1.f - z0, hcur.x, z0 * gact(hid.x));
        hcur.y = fmaf(1.f - z1, hcur.y, z1 * gact(hid.y));
        hcur.z = fmaf(1.f - z2, hcur.z, z2 * gact(hid.z));
        hcur.w = fmaf(1.f - z3, hcur.w, z3 * gact(hid.w));

        const size_t idx = obase + (size_t)j * (HD / 4);
        float4 ipv;
        if (ip_f32) ipv = ((const float4*)inp)[idx];
        else        ipv = h4_to_f4(((const h4*)inp)[idx]);
        const float4 o = { hcur.x + ipv.x, hcur.y + ipv.y,
                           hcur.z + ipv.z, hcur.w + ipv.w };
        if (out_f32) {
            ((float4*)outp)[idx] = o;
        } else {
            h4 ov;
            ov.a = __floats2half2_rn(o.x, o.y);
            ov.b = __floats2half2_rn(o.z, o.w);
            ((h4*)outp)[idx] = ov;
        }
    }
    if (tc == SC_NC - 1) *(float4*)(finals + b * HD + 4 * p) = hcur;
}

// ---------------------------------------------------------------------------
extern "C" void kernel_launch(void* const* d_in, const int* in_sizes, int n_in,
                              void* d_out, int out_size)
{
    const float* x  = (const float*)d_in[0];
    const float* h  = (const float*)d_in[1];
    const float* W0 = (const float*)d_in[2];
    const float* b0 = (const float*)d_in[3];
    const float* Wl = (const float*)d_in[4];
    const float* bl = (const float*)d_in[5];

    float* out    = (float*)d_out;
    float* finals = out + (size_t)MD * HD;

    __half *gh, *s0, *s1, *wh;
    cudaGetSymbolAddress((void**)&gh, g_gh);
    cudaGetSymbolAddress((void**)&s0, g_s0);
    cudaGetSymbolAddress((void**)&s1, g_s1);
    cudaGetSymbolAddress((void**)&wh, g_wh);

    cudaFuncSetAttribute(gemm_mma, cudaFuncAttributeMaxDynamicSharedMemorySize,
                         SMEM_TOTAL);

    conv_w<<<512, 256>>>(W0, Wl, wh);
    conv_x<<<512, 256>>>((const float4*)x, (__half2*)s0, (size_t)MD * DD / 4);

    const dim3 ggrid(ED / N_TILE, MD / M_TILE);         // (16, 128)
    const dim3 sgrid(HD / 4 / SC_LANES, BD);            // (32, 8)

    __half* Astream[LAYERS + 1] = { s0, s1, s0, s1, s0 };
    for (int l = 0; l < LAYERS; l++) {
        const size_t woff = (size_t)l * ED * DD;
        const float* bb = (l == 0) ? b0 : bl + (size_t)(l - 1) * ED;
        const int last = (l == LAYERS - 1);

        gemm_mma<<<ggrid, 256, SMEM_TOTAL>>>(Astream[l], wh + woff, bb, gh);
        scan_f4<<<sgrid, 1024>>>(
            (const h4*)gh,
            (l == 0) ? (const void*)x : (const void*)Astream[l],
            h + (size_t)l * BD * HD,
            last ? (void*)out : (void*)Astream[l + 1],
            finals + (size_t)l * BD * HD,
            (l == 0) ? 1 : 0, last ? 1 : 0);
    }
}

// round 17
// speedup vs baseline: 2.8180x; 1.0890x over previous
#include <cuda_runtime.h>
#include <cuda_fp16.h>
#include <cstdint>

#define BD 8
#define SD 2048
#define DD 1024
#define HD 1024
#define ED 2048
#define MD (BD * SD)
#define LAYERS 4

#define M_TILE 128
#define N_TILE 128
#define K_CHUNK 64
#define NCHUNK (DD / K_CHUNK)     // 16

#define ROW_B 144
#define A_TILE_B (128 * ROW_B)
#define W_TILE_B (128 * ROW_B)
#define A_OFF 0
#define W_OFF A_TILE_B
#define STAGE_B (A_TILE_B + W_TILE_B)   // 36864
#define NSTAGE 3
#define SMEM_TOTAL (NSTAGE * STAGE_B)   // 110592 -> 2 CTAs/SM

// epilogue staging: 128 rows x 136 half2-pairs? use 128 x (128+8) halfs
#define EP_ROW_H 136                    // halfs per staged row (16B pad)

__device__ __half g_gh[(size_t)MD * ED];
__device__ __half g_s0[(size_t)MD * HD];
__device__ __half g_s1[(size_t)MD * HD];
__device__ __half g_wh[(size_t)LAYERS * ED * DD];

__device__ __forceinline__ uint32_t smem_u32(const void* p) {
    uint32_t a;
    asm("{ .reg .u64 t; cvta.to.shared.u64 t, %1; cvt.u32.u64 %0, t; }"
        : "=r"(a) : "l"(p));
    return a;
}
__device__ __forceinline__ void cp16(uint32_t dst, const void* src) {
    asm volatile("cp.async.cg.shared.global [%0], [%1], 16;" :: "r"(dst), "l"(src));
}
__device__ __forceinline__ void ldsm4(uint32_t* r, uint32_t addr) {
    asm volatile("ldmatrix.sync.aligned.m8n8.x4.shared.b16 {%0,%1,%2,%3}, [%4];"
                 : "=r"(r[0]), "=r"(r[1]), "=r"(r[2]), "=r"(r[3]) : "r"(addr));
}
__device__ __forceinline__ void mma16816(float* c, const uint32_t* a,
                                         uint32_t b0, uint32_t b1) {
    asm volatile(
        "mma.sync.aligned.m16n8k16.row.col.f32.f16.f16.f32 "
        "{%0,%1,%2,%3}, {%4,%5,%6,%7}, {%8,%9}, {%0,%1,%2,%3};"
        : "+f"(c[0]), "+f"(c[1]), "+f"(c[2]), "+f"(c[3])
        : "r"(a[0]), "r"(a[1]), "r"(a[2]), "r"(a[3]), "r"(b0), "r"(b1));
}

// ---------------------------------------------------------------------------
// GEMM (R12 mainloop): CTA 128x128, 8 warps (2x4), warp 64x32, K_CHUNK=64,
// 3-stage ring, 2 CTAs/SM. Epilogue staged via smem for coalesced stores.
// ---------------------------------------------------------------------------
__global__ __launch_bounds__(256, 2) void gemm_mma(
    const __half* __restrict__ A, const __half* __restrict__ W,
    const float* __restrict__ bias, __half* __restrict__ C)
{
    extern __shared__ char smem[];
    const uint32_t sbase = smem_u32(smem);
    const int tid  = threadIdx.x;
    const int wid  = tid >> 5;
    const int lane = tid & 31;
    const int g    = lane >> 2;
    const int t4   = lane & 3;
    const int wm   = wid >> 2;
    const int wn   = wid & 3;
    const int bm   = blockIdx.y * M_TILE;
    const int bn   = blockIdx.x * N_TILE;

    float acc[4][4][4];
#pragma unroll
    for (int i = 0; i < 4; i++)
#pragma unroll
        for (int j = 0; j < 4; j++)
#pragma unroll
            for (int q = 0; q < 4; q++) acc[i][j][q] = 0.f;

    auto fill = [&](int s, int c) {
        const uint32_t st = sbase + s * STAGE_B;
        const int k0 = c * K_CHUNK;
#pragma unroll
        for (int rep = 0; rep < 4; rep++) {
            const int v  = tid + rep * 256;
            const int r  = v >> 3, c8 = v & 7;
            cp16(st + A_OFF + r * ROW_B + c8 * 16,
                 A + (size_t)(bm + r) * DD + k0 + c8 * 8);
        }
#pragma unroll
        for (int rep = 0; rep < 4; rep++) {
            const int v  = tid + rep * 256;
            const int r  = v >> 3, c8 = v & 7;
            cp16(st + W_OFF + r * ROW_B + c8 * 16,
                 W + (size_t)(bn + r) * DD + k0 + c8 * 8);
        }
        asm volatile("cp.async.commit_group;" ::: "memory");
    };

    const uint32_t a_off = (uint32_t)(wm * 64 + (lane & 15)) * ROW_B
                         + ((lane >> 4) & 1) * 16;
    const uint32_t w_mi  = (uint32_t)(lane >> 3);
    const uint32_t w_off = (uint32_t)(wn * 32 + (w_mi >> 1) * 8 + (lane & 7)) * ROW_B
                         + (w_mi & 1) * 16;

    fill(0, 0);
    fill(1, 1);

#pragma unroll 1
    for (int c = 0; c < NCHUNK; c++) {
        if (c + 1 < NCHUNK)
            asm volatile("cp.async.wait_group 1;" ::: "memory");
        else
            asm volatile("cp.async.wait_group 0;" ::: "memory");
        __syncthreads();

        if (c + 2 < NCHUNK) fill((c + 2) % NSTAGE, c + 2);

        const uint32_t st = sbase + (c % NSTAGE) * STAGE_B;
#pragma unroll
        for (int k16 = 0; k16 < 4; k16++) {
            const uint32_t kb = (uint32_t)k16 * 32;
            uint32_t wf[2][4];
#pragma unroll
            for (int jp = 0; jp < 2; jp++)
                ldsm4(wf[jp], st + W_OFF + w_off + jp * (16 * ROW_B) + kb);
#pragma unroll
            for (int mi = 0; mi < 4; mi++) {
                uint32_t af[4];
                ldsm4(af, st + A_OFF + a_off + mi * (16 * ROW_B) + kb);
#pragma unroll
                for (int jp = 0; jp < 2; jp++) {
                    mma16816(acc[mi][jp * 2],     af, wf[jp][0], wf[jp][1]);
                    mma16816(acc[mi][jp * 2 + 1], af, wf[jp][2], wf[jp][3]);
                }
            }
        }
    }
    __syncthreads();   // mainloop smem no longer needed; reuse as staging

    // stage C tile (with bias) in smem as half
    __half* ep = (__half*)smem;
    {
        float bj[4][2];
#pragma unroll
        for (int j = 0; j < 4; j++) {
            const int col = wn * 32 + j * 8 + 2 * t4;
            bj[j][0] = bias[bn + col]; bj[j][1] = bias[bn + col + 1];
        }
#pragma unroll
        for (int mi = 0; mi < 4; mi++) {
            const int r0 = wm * 64 + mi * 16 + g;
#pragma unroll
            for (int j = 0; j < 4; j++) {
                const int col = wn * 32 + j * 8 + 2 * t4;
                *(__half2*)(ep + (size_t)r0 * EP_ROW_H + col) =
                    __floats2half2_rn(acc[mi][j][0] + bj[j][0],
                                      acc[mi][j][1] + bj[j][1]);
                *(__half2*)(ep + (size_t)(r0 + 8) * EP_ROW_H + col) =
                    __floats2half2_rn(acc[mi][j][2] + bj[j][0],
                                      acc[mi][j][3] + bj[j][1]);
            }
        }
    }
    __syncthreads();

    // coalesced 16B stores: 128 rows x 16 chunks of 8 halfs
#pragma unroll
    for (int rep = 0; rep < 8; rep++) {
        const int v   = tid + rep * 256;     // 0..2047
        const int r   = v >> 4;
        const int c16 = v & 15;
        const uint4 val = *(const uint4*)(ep + (size_t)r * EP_ROW_H + c16 * 8);
        *(uint4*)(C + (size_t)(bm + r) * ED + bn + c16 * 8) = val;
    }
}

// ---------------------------------------------------------------------------
__global__ __launch_bounds__(256) void conv_x(
    const float4* __restrict__ src, __half2* __restrict__ dst, size_t n4)
{
    for (size_t i = (size_t)blockIdx.x * blockDim.x + threadIdx.x; i < n4;
         i += (size_t)gridDim.x * blockDim.x) {
        const float4 v = src[i];
        dst[2 * i]     = __floats2half2_rn(v.x, v.y);
        dst[2 * i + 1] = __floats2half2_rn(v.z, v.w);
    }
}

__global__ __launch_bounds__(256) void conv_w(
    const float* __restrict__ W0, const float* __restrict__ Wl,
    __half* __restrict__ dst)
{
    const size_t per = (size_t)ED * DD;
    const size_t n = (size_t)LAYERS * per;
    for (size_t i = (size_t)blockIdx.x * blockDim.x + threadIdx.x; i < n;
         i += (size_t)gridDim.x * blockDim.x)
        dst[i] = __float2half_rn((i < per) ? W0[i] : Wl[i - per]);
}

// ---------------------------------------------------------------------------
// Scan half2 (measured-best): 16 h2-lanes x 64 chunks, tanh sigmoid.
// ---------------------------------------------------------------------------
__device__ __forceinline__ float sigf(float x) {
    float t;
    asm("tanh.approx.f32 %0, %1;" : "=f"(t) : "f"(0.5f * x));
    return fmaf(0.5f, t, 0.5f);
}
__device__ __forceinline__ float gact(float x) { return (x >= 0.f) ? (x + 0.5f) : sigf(x); }

#define SC_LANES 16
#define SC_NC    64
#define SC_CH    (SD / SC_NC)   // 32

__global__ __launch_bounds__(1024) void scan_h2(
    const __half2* __restrict__ gh,
    const void* __restrict__ inp,
    const float* __restrict__ h0,
    void* __restrict__ outp,
    float* __restrict__ finals, int ip_f32, int out_f32)
{
    const int b  = blockIdx.y;
    const int hx = threadIdx.x & (SC_LANES - 1);
    const int tc = threadIdx.x / SC_LANES;
    const int p  = blockIdx.x * SC_LANES + hx;
    const int t0 = tc * SC_CH;

    const size_t rowbase = (size_t)b * SD;
    const __half2* gp = gh + (rowbase + t0) * (ED / 2) + p;
    const __half2* hp = gp + HD / 2;

    float2 Ac = {1.f, 1.f}, Cc = {0.f, 0.f};
#pragma unroll 8
    for (int j = 0; j < SC_CH; j++) {
        const size_t off = (size_t)j * (ED / 2);
        const float2 zg  = __half22float2(gp[off]);
        const float2 hid = __half22float2(hp[off]);
        const float zx = sigf(zg.x), zy = sigf(zg.y);
        const float ax = 1.f - zx, ay = 1.f - zy;
        Cc.x = fmaf(ax, Cc.x, zx * gact(hid.x));
        Cc.y = fmaf(ay, Cc.y, zy * gact(hid.y));
        Ac.x *= ax; Ac.y *= ay;
    }

    __shared__ float2 sA[SC_NC][SC_LANES + 1], sC[SC_NC][SC_LANES + 1];
    sA[tc][hx] = Ac; sC[tc][hx] = Cc;
    __syncthreads();

    const float2 hprev = *(const float2*)(h0 + b * HD + 2 * p);
    float2 hcur = { gact(hprev.x), gact(hprev.y) };
    for (int c = 0; c < tc; c++) {
        const float2 a = sA[c][hx], cc = sC[c][hx];
        hcur.x = fmaf(a.x, hcur.x, cc.x);
        hcur.y = fmaf(a.y, hcur.y, cc.y);
    }

    const size_t obase = (rowbase + t0) * (HD / 2) + p;
#pragma unroll 8
    for (int j = 0; j < SC_CH; j++) {
        const size_t off = (size_t)j * (ED / 2);
        const float2 zg  = __half22float2(gp[off]);
        const float2 hid = __half22float2(hp[off]);
        const float zx = sigf(zg.x), zy = sigf(zg.y);
        hcur.x = fmaf(1.f - zx, hcur.x, zx * gact(hid.x));
        hcur.y = fmaf(1.f - zy, hcur.y, zy * gact(hid.y));

        const size_t idx = obase + (size_t)j * (HD / 2);
        float2 ipv;
        if (ip_f32) ipv = ((const float2*)inp)[idx];
        else        ipv = __half22float2(((const __half2*)inp)[idx]);
        const float2 o = { hcur.x + ipv.x, hcur.y + ipv.y };
        if (out_f32) ((float2*)outp)[idx] = o;
        else         ((__half2*)outp)[idx] = __floats2half2_rn(o.x, o.y);
    }
    if (tc == SC_NC - 1) *(float2*)(finals + b * HD + 2 * p) = hcur;
}

// ---------------------------------------------------------------------------
extern "C" void kernel_launch(void* const* d_in, const int* in_sizes, int n_in,
                              void* d_out, int out_size)
{
    const float* x  = (const float*)d_in[0];
    const float* h  = (const float*)d_in[1];
    const float* W0 = (const float*)d_in[2];
    const float* b0 = (const float*)d_in[3];
    const float* Wl = (const float*)d_in[4];
    const float* bl = (const float*)d_in[5];

    float* out    = (float*)d_out;
    float* finals = out + (size_t)MD * HD;

    __half *gh, *s0, *s1, *wh;
    cudaGetSymbolAddress((void**)&gh, g_gh);
    cudaGetSymbolAddress((void**)&s0, g_s0);
    cudaGetSymbolAddress((void**)&s1, g_s1);
    cudaGetSymbolAddress((void**)&wh, g_wh);

    cudaFuncSetAttribute(gemm_mma, cudaFuncAttributeMaxDynamicSharedMemorySize,
                         SMEM_TOTAL);

    conv_w<<<512, 256>>>(W0, Wl, wh);
    conv_x<<<512, 256>>>((const float4*)x, (__half2*)s0, (size_t)MD * DD / 4);

    const dim3 ggrid(ED / N_TILE, MD / M_TILE);         // (16, 128)
    const dim3 sgrid(HD / 2 / SC_LANES, BD);            // (32, 8)

    __half* Astream[LAYERS + 1] = { s0, s1, s0, s1, s0 };
    for (int l = 0; l < LAYERS; l++) {
        const size_t woff = (size_t)l * ED * DD;
        const float* bb = (l == 0) ? b0 : bl + (size_t)(l - 1) * ED;
        const int last = (l == LAYERS - 1);

        gemm_mma<<<ggrid, 256, SMEM_TOTAL>>>(Astream[l], wh + woff, bb, gh);
        scan_h2<<<sgrid, 1024>>>(
            (const __half2*)gh,
            (l == 0) ? (const void*)x : (const void*)Astream[l],
            h + (size_t)l * BD * HD,
            last ? (void*)out : (void*)Astream[l + 1],
            finals + (size_t)l * BD * HD,
            (l == 0) ? 1 : 0, last ? 1 : 0);
    }
}